// round 6
// baseline (speedup 1.0000x reference)
#include <cuda_runtime.h>
#include <math.h>
#include <stdint.h>

#define BB    1024     // batch rows
#define NN    8192     // samples per row
#define MM2   900      // half fold period (parity decimation)
#define NB    140      // bpm bins
#define NBP   144      // padded bins
#define SLAB  15       // m per smem slab
#define NSTEP 60       // slabs (60*15 = 900)
#define ROWS  8        // rows per dft block
#define NTILE 128      // dft blocks (128*8 = 1024 rows)

// ---------------- device scratch ----------------
__device__ float2 d_fold[(size_t)BB * MM2];   // (ge, go) per (row, m)
__device__ float  d_tl[BB];                   // per-row (1 - pearson)
__device__ float  d_fl[BB];                   // per-row (ce + kl)
__device__ unsigned int d_done;

typedef unsigned long long ull;

// ---------------- f32x2 helpers ----------------
__device__ __forceinline__ ull pk2(float lo, float hi) {
    ull r;
    asm("mov.b64 %0, {%1, %2};" : "=l"(r) : "f"(lo), "f"(hi));
    return r;
}
__device__ __forceinline__ void fma2(ull& d, ull a, ull b) {
    asm("fma.rn.f32x2 %0, %1, %2, %0;" : "+l"(d) : "l"(a), "l"(b));
}

// ---------------- warp helpers ----------------
__device__ __forceinline__ float wsum(float v) {
    #pragma unroll
    for (int o = 16; o; o >>= 1) v += __shfl_down_sync(0xffffffffu, v, o);
    return v;
}
__device__ __forceinline__ float wallsum(float v) {
    #pragma unroll
    for (int o = 16; o; o >>= 1) v += __shfl_xor_sync(0xffffffffu, v, o);
    return v;
}
__device__ __forceinline__ float wallmax(float v) {
    #pragma unroll
    for (int o = 16; o; o >>= 1) v = fmaxf(v, __shfl_xor_sync(0xffffffffu, v, o));
    return v;
}

// ---------------- K1: pearson sums + parity fold + inline hann --------------
__global__ void __launch_bounds__(256) k_fold(const float* __restrict__ x,
                                              const float* __restrict__ y) {
    __shared__ float red[8][5];
    int b = blockIdx.x;
    int tid = threadIdx.x;
    int lane = tid & 31, warp = tid >> 5;

    if (b == 0 && tid == 0) d_done = 0;     // ticket reset for this replay

    const float* xr = x + (size_t)b * NN;
    const float* yr = y + (size_t)b * NN;
    const float W = 3.8349520e-4f;          // pi/8191

    float sx = 0.f, sy = 0.f, sxy = 0.f, sxx = 0.f, syy = 0.f;

    #pragma unroll 1
    for (int m = tid; m < MM2; m += 256) {
        float ge = 0.f, go = 0.f;
        #pragma unroll
        for (int j = 0; j < 10; j++) {
            int n = m + 900 * j;
            if (j < 9 || n < NN) {
                float xv = xr[n], yv = yr[n];
                sx  += xv;       sy  += yv;
                sxy += xv * yv;  sxx += xv * xv;  syy += yv * yv;
                float s = __sinf((float)n * W);
                float hx = xv * s * s;
                ge += hx;
                go += (j & 1) ? -hx : hx;
            }
        }
        d_fold[(size_t)b * MM2 + m] = make_float2(ge, go);
    }

    sx = wsum(sx); sy = wsum(sy); sxy = wsum(sxy); sxx = wsum(sxx); syy = wsum(syy);
    if (lane == 0) { red[warp][0]=sx; red[warp][1]=sy; red[warp][2]=sxy; red[warp][3]=sxx; red[warp][4]=syy; }
    __syncthreads();
    if (tid == 0) {
        double SX=0, SY=0, SXY=0, SXX=0, SYY=0;
        #pragma unroll
        for (int w = 0; w < 8; w++) {
            SX += red[w][0]; SY += red[w][1]; SXY += red[w][2];
            SXX += red[w][3]; SYY += red[w][4];
        }
        double num = (double)NN * SXY - SX * SY;
        double den = sqrt(((double)NN * SXX - SX * SX) * ((double)NN * SYY - SY * SY));
        d_tl[b] = (float)(1.0 - num / den);
    }
}

// ---------------- K2: full-900m NUDFT per 8-row tile + fused loss -----------
// grid 128, block 288 = 36 tx * 8 ty; thread: 1 row x 4 bins (tx,+36,+72,+108)
__global__ void __launch_bounds__(288, 1) k_dft(const int* __restrict__ hr,
                                                const int* __restrict__ epoch_p,
                                                float* __restrict__ out) {
    __shared__ float sTab[SLAB][2 * NBP];     // 15 m x 144 bins x (s,c) = 17.3 KB
    __shared__ float sGe[SLAB][ROWS];
    __shared__ float sGo[SLAB][ROWS];
    __shared__ float2 sSpec[ROWS][NBP];       // 9.2 KB

    int tile = blockIdx.x;
    int rowBase = tile * ROWS;
    int tid = threadIdx.x;
    int tx = tid % 36;
    int ty = tid / 36;                        // 0..7 -> row within tile
    int lane = tid & 31, warp = tid >> 5;

    // table-gen assignment: bin bk, alternating mi starting at `half`
    int bk = tid % NBP;
    int half = tid / NBP;                     // 0 or 1
    int f = 40 + bk;
    int st2 = 2 * f;                          // < 1800

    ull acc[4] = {};
    const float* gplane = (tx & 1) ? &sGo[0][0] : &sGe[0][0];
    const float ASCALE = 3.4906585e-3f;       // 2*pi/1800

    for (int step = 0; step < NSTEP; step++) {
        int m0 = step * SLAB;
        __syncthreads();
        // table slab: exact integer angle recurrence + fast sincos
        {
            int rr = (f * (m0 + half)) % 1800;
            #pragma unroll
            for (int mi = half; mi < SLAB; mi += 2) {
                int rf = (rr >= 900) ? rr - 1800 : rr;
                float s, c;
                __sincosf((float)rf * ASCALE, &s, &c);
                ((ull*)&sTab[mi][0])[bk] = pk2(s, c);
                rr += st2; if (rr >= 1800) rr -= 1800;
            }
        }
        // g slab: 120 float2 loads (8 rows x 15 m)
        if (tid < ROWS * SLAB) {
            int r = tid / SLAB, mi = tid % SLAB;
            float2 v = d_fold[(size_t)(rowBase + r) * MM2 + m0 + mi];
            sGe[mi][r] = v.x;
            sGo[mi][r] = v.y;
        }
        __syncthreads();

        #pragma unroll
        for (int mi = 0; mi < SLAB; mi++) {
            float g = gplane[mi * ROWS + ty];
            const ull* trow = (const ull*)&sTab[mi][0];
            ull g2 = pk2(g, g);
            fma2(acc[0], g2, trow[tx]);
            fma2(acc[1], g2, trow[tx + 36]);
            fma2(acc[2], g2, trow[tx + 72]);
            fma2(acc[3], g2, trow[tx + 108]);
        }
    }

    // deposit spectrum in smem
    __syncthreads();
    {
        ull* sp = (ull*)&sSpec[ty][0];
        sp[tx]       = acc[0];
        sp[tx + 36]  = acc[1];
        sp[tx + 72]  = acc[2];
        sp[tx + 108] = acc[3];
    }
    __syncthreads();

    // ---- fused loss: warp w (w<8) handles row rowBase+w ----
    if (warp < ROWS) {
        int row = rowBase + warp;
        const float2* sp = &sSpec[warp][0];

        float ca[5]; bool valid[5];
        float tot = 0.f;
        #pragma unroll
        for (int j = 0; j < 5; j++) {
            int k = lane + 32 * j;
            valid[j] = (k < NB);
            float2 v = valid[j] ? sp[k] : make_float2(0.f, 0.f);
            ca[j] = v.x * v.x + v.y * v.y;
            if (valid[j]) tot += ca[j];
        }
        tot = wallsum(tot);

        float logits[5]; float mx = -1e30f;
        #pragma unroll
        for (int j = 0; j < 5; j++) {
            logits[j] = ca[j] / tot;
            if (valid[j]) mx = fmaxf(mx, logits[j]);
        }
        mx = wallmax(mx);
        float se = 0.f;
        #pragma unroll
        for (int j = 0; j < 5; j++)
            if (valid[j]) se += expf(logits[j] - mx);
        se = wallsum(se);
        float lse = mx + logf(se);

        int h = hr[row];
        float lh = 0.f;
        #pragma unroll
        for (int j = 0; j < 5; j++) {
            int k = lane + 32 * j;
            if (valid[j] && k == h) lh = logits[j];
        }
        lh = wallsum(lh);
        float ce = lse - lh;

        float hf = (float)h;
        float klp = 0.f;
        #pragma unroll
        for (int j = 0; j < 5; j++) {
            if (valid[j]) {
                int k = lane + 32 * j;
                float dd = (float)k - hf;
                float t = expf(-0.5f * dd * dd) * 0.3989422804014327f;
                t = fmaxf(t, 1e-15f);
                klp += expf(t) * (t - (logits[j] - lse));
            }
        }
        klp = wallsum(klp);
        if (lane == 0) d_fl[row] = ce + klp / (float)NB;
    }

    // ---- last-block final scalar ----
    __threadfence();
    __syncthreads();
    __shared__ unsigned int sTicket;
    if (tid == 0) sTicket = atomicAdd(&d_done, 1u);
    __syncthreads();
    if (sTicket != NTILE - 1) return;
    __threadfence();

    float a = 0.f, cc = 0.f;
    for (int i = tid; i < BB; i += 288) { a += d_tl[i]; cc += d_fl[i]; }
    a = wallsum(a); cc = wallsum(cc);
    __shared__ float sA[9], sC[9];
    if (lane == 0) { sA[warp] = a; sC[warp] = cc; }
    __syncthreads();
    if (tid == 0) {
        double TA = 0.0, TC = 0.0;
        #pragma unroll
        for (int w = 0; w < 9; w++) { TA += sA[w]; TC += sC[w]; }
        double tl = TA / (double)BB;
        double fl = TC / (double)BB;
        int epoch = epoch_p[0];
        double alpha, beta;
        if (epoch > 25) { alpha = 0.05; beta = 2.0; }
        else {
            alpha = 0.1 * pow(0.5, (double)epoch / 25.0);
            beta  = pow(2.0, (double)epoch / 25.0);
        }
        out[0] = (float)(alpha * tl + beta * fl);
    }
}

// ---------------- launch ----------------
extern "C" void kernel_launch(void* const* d_in, const int* in_sizes, int n_in,
                              void* d_out, int out_size) {
    const int*   epoch_p = nullptr;
    const float* xp = nullptr;
    const float* yp = nullptr;
    const int*   hrp = nullptr;
    for (int i = 0; i < n_in; i++) {
        if (in_sizes[i] == 1 && !epoch_p) epoch_p = (const int*)d_in[i];
        else if (in_sizes[i] == BB * NN) { if (!xp) xp = (const float*)d_in[i]; else yp = (const float*)d_in[i]; }
        else if (in_sizes[i] == BB) hrp = (const int*)d_in[i];
    }
    float* out = (float*)d_out;

    k_fold<<<BB, 256>>>(xp, yp);
    k_dft<<<NTILE, 288>>>(hrp, epoch_p, out);
    (void)out_size;
}

// round 7
// speedup vs baseline: 1.6083x; 1.6083x over previous
#include <cuda_runtime.h>
#include <math.h>
#include <stdint.h>

#define BB    1024     // batch rows
#define NN    8192     // samples per row
#define MM2   900      // half fold period (parity decimation)
#define NB    140      // bpm bins
#define NBP   144      // padded bins
#define NCH   9        // m-chunks
#define CHM   100      // m per chunk (9*100 = 900)
#define SLAB  10       // m per smem slab
#define NTILE 32       // row tiles (32 rows each)

// ---------------- device scratch ----------------
__device__ float  d_hann[NN];
__device__ float2 d_fold[(size_t)BB * MM2];             // (ge, go)
__device__ float2 d_part[(size_t)BB * NCH * NBP];       // [row][chunk][bin] (s,c)
__device__ float  d_tl[BB];
__device__ float  d_fl[BB];
__device__ unsigned int d_tdone[NTILE];
__device__ unsigned int d_done;

typedef unsigned long long ull;

// ---------------- f32x2 helpers ----------------
__device__ __forceinline__ ull pk2(float lo, float hi) {
    ull r;
    asm("mov.b64 %0, {%1, %2};" : "=l"(r) : "f"(lo), "f"(hi));
    return r;
}
__device__ __forceinline__ void fma2(ull& d, ull a, ull b) {
    asm("fma.rn.f32x2 %0, %1, %2, %0;" : "+l"(d) : "l"(a), "l"(b));
}

// ---------------- warp helpers ----------------
__device__ __forceinline__ float wsum(float v) {
    #pragma unroll
    for (int o = 16; o; o >>= 1) v += __shfl_down_sync(0xffffffffu, v, o);
    return v;
}
__device__ __forceinline__ float wallsum(float v) {
    #pragma unroll
    for (int o = 16; o; o >>= 1) v += __shfl_xor_sync(0xffffffffu, v, o);
    return v;
}
__device__ __forceinline__ float wallmax(float v) {
    #pragma unroll
    for (int o = 16; o; o >>= 1) v = fmaxf(v, __shfl_xor_sync(0xffffffffu, v, o));
    return v;
}

// ---------------- K0: hann table + ticket resets ----------------
__global__ void __launch_bounds__(256) k_init() {
    int n = blockIdx.x * 256 + threadIdx.x;
    if (n < NN) {
        float s = sinf((float)n * 3.8349520e-4f);   // pi/8191
        d_hann[n] = s * s;
    }
    if (n < NTILE) d_tdone[n] = 0;
    if (n == NTILE) d_done = 0;
}

// ---------------- K1: pearson sums + parity fold, float4-vectorized ----------
// thread t<225 handles m in {4t..4t+3}; n = 4*(t + 225*j) stays 16B-aligned
__global__ void __launch_bounds__(256) k_fold(const float* __restrict__ x,
                                              const float* __restrict__ y) {
    __shared__ float red[8][5];
    int b = blockIdx.x;
    int tid = threadIdx.x;
    int lane = tid & 31, warp = tid >> 5;

    const float4* xr = (const float4*)(x + (size_t)b * NN);
    const float4* yr = (const float4*)(y + (size_t)b * NN);
    const float4* hr4 = (const float4*)d_hann;

    float sx = 0.f, sy = 0.f, sxy = 0.f, sxx = 0.f, syy = 0.f;
    float ge[4] = {}, go[4] = {};

    if (tid < 225) {
        #pragma unroll
        for (int j = 0; j < 10; j++) {
            int q = tid + 225 * j;                   // float4 index
            if (j < 9 || q < 2048) {
                float4 xv = xr[q];
                float4 yv = yr[q];
                float4 hv = hr4[q];
                sx += xv.x + xv.y + xv.z + xv.w;
                sy += yv.x + yv.y + yv.z + yv.w;
                sxy += xv.x*yv.x + xv.y*yv.y + xv.z*yv.z + xv.w*yv.w;
                sxx += xv.x*xv.x + xv.y*xv.y + xv.z*xv.z + xv.w*xv.w;
                syy += yv.x*yv.x + yv.y*yv.y + yv.z*yv.z + yv.w*yv.w;
                float h0 = xv.x * hv.x, h1 = xv.y * hv.y;
                float h2 = xv.z * hv.z, h3 = xv.w * hv.w;
                ge[0] += h0; ge[1] += h1; ge[2] += h2; ge[3] += h3;
                if (j & 1) { go[0] -= h0; go[1] -= h1; go[2] -= h2; go[3] -= h3; }
                else       { go[0] += h0; go[1] += h1; go[2] += h2; go[3] += h3; }
            }
        }
        float4* dst = (float4*)(d_fold + (size_t)b * MM2 + 4 * tid);
        dst[0] = make_float4(ge[0], go[0], ge[1], go[1]);
        dst[1] = make_float4(ge[2], go[2], ge[3], go[3]);
    }

    sx = wsum(sx); sy = wsum(sy); sxy = wsum(sxy); sxx = wsum(sxx); syy = wsum(syy);
    if (lane == 0) { red[warp][0]=sx; red[warp][1]=sy; red[warp][2]=sxy; red[warp][3]=sxx; red[warp][4]=syy; }
    __syncthreads();
    if (tid == 0) {
        double SX=0, SY=0, SXY=0, SXX=0, SYY=0;
        #pragma unroll
        for (int w = 0; w < 8; w++) {
            SX += red[w][0]; SY += red[w][1]; SXY += red[w][2];
            SXX += red[w][3]; SYY += red[w][4];
        }
        double num = (double)NN * SXY - SX * SY;
        double den = sqrt(((double)NN * SXX - SX * SX) * ((double)NN * SYY - SY * SY));
        d_tl[b] = (float)(1.0 - num / den);
    }
}

// ---------------- K2: parity NUDFT (R4 geometry) + fused tile loss ----------
// grid (32 tiles, 9 chunks), block 288 = 36 tx * 8 ty; tile 4 rows x 4 bins
__global__ void __launch_bounds__(288, 2) k_dft(const int* __restrict__ hr,
                                                const int* __restrict__ epoch_p,
                                                float* __restrict__ out) {
    __shared__ float sTab[SLAB * 2 * NBP];    // 10 m x 144 bins x (s,c)
    __shared__ float sGe[SLAB][32];
    __shared__ float sGo[SLAB][32];

    int tile  = blockIdx.x;
    int chunk = blockIdx.y;
    int tid = threadIdx.x;
    int tx = tid % 36;
    int ty = tid / 36;
    int lane = tid & 31, warp = tid >> 5;

    int rowBase = tile * 32;
    int mBase = chunk * CHM;

    int bk  = tid % NBP;
    int grp = tid / NBP;
    int freq = 40 + bk;

    {
        ull acc[4][4] = {};
        const float* gp = (tx & 1) ? &sGo[0][0] : &sGe[0][0];
        const float ASCALE = 3.4906585e-3f;   // 2*pi/1800

        for (int step = 0; step < CHM / SLAB; step++) {
            int m0 = mBase + step * SLAB;
            __syncthreads();
            #pragma unroll
            for (int i = 0; i < 5; i++) {
                int mi = grp * 5 + i;
                float s = 0.f, c = 0.f;
                if (bk < NB) {
                    int r = (freq * (m0 + mi)) % 1800;
                    if (r >= 900) r -= 1800;
                    __sincosf((float)r * ASCALE, &s, &c);
                }
                sTab[mi * (2 * NBP) + 2 * bk]     = s;
                sTab[mi * (2 * NBP) + 2 * bk + 1] = c;
            }
            if (tid < 160) {
                int r = tid & 31, q = tid >> 5;
                float4 v = *(const float4*)(d_fold + (size_t)(rowBase + r) * MM2 + m0 + 2 * q);
                sGe[2 * q][r]     = v.x;  sGo[2 * q][r]     = v.y;
                sGe[2 * q + 1][r] = v.z;  sGo[2 * q + 1][r] = v.w;
            }
            __syncthreads();

            #pragma unroll
            for (int mi = 0; mi < SLAB; mi++) {
                float4 g = *(const float4*)&gp[mi * 32 + 4 * ty];
                const ull* trow = (const ull*)&sTab[mi * (2 * NBP)];
                ull p0 = trow[tx];
                ull p1 = trow[tx + 36];
                ull p2 = trow[tx + 72];
                ull p3 = trow[tx + 108];
                float gr[4] = {g.x, g.y, g.z, g.w};
                #pragma unroll
                for (int r = 0; r < 4; r++) {
                    ull g2 = pk2(gr[r], gr[r]);
                    fma2(acc[r][0], g2, p0);
                    fma2(acc[r][1], g2, p1);
                    fma2(acc[r][2], g2, p2);
                    fma2(acc[r][3], g2, p3);
                }
            }
        }

        #pragma unroll
        for (int r = 0; r < 4; r++) {
            int row = rowBase + 4 * ty + r;
            ull* dst = (ull*)(d_part + ((size_t)row * NCH + chunk) * NBP);
            dst[tx]       = acc[r][0];
            dst[tx + 36]  = acc[r][1];
            dst[tx + 72]  = acc[r][2];
            dst[tx + 108] = acc[r][3];
        }
    }

    // ---- per-tile ticket: last of 9 chunk-blocks fuses the loss ----
    __threadfence();
    __syncthreads();
    __shared__ unsigned int sT;
    if (tid == 0) sT = atomicAdd(&d_tdone[tile], 1u);
    __syncthreads();
    if (sT != NCH - 1) return;
    __threadfence();

    // warps 0..7: 4 rows each (rows rowBase + 4*warp + i), fixed chunk order
    if (warp < 8) {
        #pragma unroll 1
        for (int i = 0; i < 4; i++) {
            int row = rowBase + 4 * warp + i;
            const float2* pr = d_part + (size_t)row * NCH * NBP;

            float sA[5] = {}, cA[5] = {};
            bool valid[5];
            #pragma unroll
            for (int j = 0; j < 5; j++) valid[j] = (lane + 32 * j < NB);
            #pragma unroll
            for (int ch = 0; ch < NCH; ch++) {
                #pragma unroll
                for (int j = 0; j < 5; j++) {
                    if (valid[j]) {
                        float2 v = pr[ch * NBP + lane + 32 * j];
                        sA[j] += v.x; cA[j] += v.y;
                    }
                }
            }

            float ca[5]; float tot = 0.f;
            #pragma unroll
            for (int j = 0; j < 5; j++) {
                ca[j] = sA[j] * sA[j] + cA[j] * cA[j];
                if (valid[j]) tot += ca[j];
            }
            tot = wallsum(tot);

            float logits[5]; float mx = -1e30f;
            #pragma unroll
            for (int j = 0; j < 5; j++) {
                logits[j] = ca[j] / tot;
                if (valid[j]) mx = fmaxf(mx, logits[j]);
            }
            mx = wallmax(mx);
            float se = 0.f;
            #pragma unroll
            for (int j = 0; j < 5; j++)
                if (valid[j]) se += expf(logits[j] - mx);
            se = wallsum(se);
            float lse = mx + logf(se);

            int h = hr[row];
            float lh = 0.f;
            #pragma unroll
            for (int j = 0; j < 5; j++) {
                int k = lane + 32 * j;
                if (valid[j] && k == h) lh = logits[j];
            }
            lh = wallsum(lh);
            float ce = lse - lh;

            float hf = (float)h;
            float klp = 0.f;
            #pragma unroll
            for (int j = 0; j < 5; j++) {
                if (valid[j]) {
                    int k = lane + 32 * j;
                    float dd = (float)k - hf;
                    float t = expf(-0.5f * dd * dd) * 0.3989422804014327f;
                    t = fmaxf(t, 1e-15f);
                    klp += expf(t) * (t - (logits[j] - lse));
                }
            }
            klp = wallsum(klp);
            if (lane == 0) d_fl[row] = ce + klp / (float)NB;
        }
    }

    // ---- global ticket among 32 tile-finishers: final scalar ----
    __threadfence();
    __syncthreads();
    __shared__ unsigned int sT2;
    if (tid == 0) sT2 = atomicAdd(&d_done, 1u);
    __syncthreads();
    if (sT2 != NTILE - 1) return;
    __threadfence();

    float a = 0.f, cc = 0.f;
    for (int i = tid; i < BB; i += 288) { a += d_tl[i]; cc += d_fl[i]; }
    a = wallsum(a); cc = wallsum(cc);
    __shared__ float sA9[9], sC9[9];
    if (lane == 0) { sA9[warp] = a; sC9[warp] = cc; }
    __syncthreads();
    if (tid == 0) {
        double TA = 0.0, TC = 0.0;
        #pragma unroll
        for (int w = 0; w < 9; w++) { TA += sA9[w]; TC += sC9[w]; }
        double tl = TA / (double)BB;
        double fl = TC / (double)BB;
        int epoch = epoch_p[0];
        double alpha, beta;
        if (epoch > 25) { alpha = 0.05; beta = 2.0; }
        else {
            alpha = 0.1 * pow(0.5, (double)epoch / 25.0);
            beta  = pow(2.0, (double)epoch / 25.0);
        }
        out[0] = (float)(alpha * tl + beta * fl);
    }
}

// ---------------- launch ----------------
extern "C" void kernel_launch(void* const* d_in, const int* in_sizes, int n_in,
                              void* d_out, int out_size) {
    const int*   epoch_p = nullptr;
    const float* xp = nullptr;
    const float* yp = nullptr;
    const int*   hrp = nullptr;
    for (int i = 0; i < n_in; i++) {
        if (in_sizes[i] == 1 && !epoch_p) epoch_p = (const int*)d_in[i];
        else if (in_sizes[i] == BB * NN) { if (!xp) xp = (const float*)d_in[i]; else yp = (const float*)d_in[i]; }
        else if (in_sizes[i] == BB) hrp = (const int*)d_in[i];
    }
    float* out = (float*)d_out;

    k_init<<<(NN + 255) / 256, 256>>>();
    k_fold<<<BB, 256>>>(xp, yp);
    k_dft<<<dim3(NTILE, NCH), 288>>>(hrp, epoch_p, out);
    (void)out_size;
}

// round 8
// speedup vs baseline: 1.9148x; 1.1906x over previous
#include <cuda_runtime.h>
#include <math.h>
#include <stdint.h>

#define BB    1024     // batch rows
#define NN    8192     // samples per row
#define MM2   900      // half fold period (parity decimation)
#define NB    140      // bpm bins
#define NBP   144      // padded bins
#define NCH   9        // m-chunks
#define CHM   100      // m per chunk (9*100 = 900)
#define SLAB  10       // m per smem slab

// ---------------- device scratch ----------------
__device__ float2 d_fold[(size_t)BB * MM2];             // (ge, go)
__device__ float2 d_part[(size_t)BB * NCH * NBP];       // [row][chunk][bin] (s,c)
__device__ float  d_tl[BB];
__device__ float  d_fl[BB];

typedef unsigned long long ull;

// ---------------- f32x2 helpers ----------------
__device__ __forceinline__ ull pk2(float lo, float hi) {
    ull r;
    asm("mov.b64 %0, {%1, %2};" : "=l"(r) : "f"(lo), "f"(hi));
    return r;
}
__device__ __forceinline__ void fma2(ull& d, ull a, ull b) {
    asm("fma.rn.f32x2 %0, %1, %2, %0;" : "+l"(d) : "l"(a), "l"(b));
}

// ---------------- warp helpers ----------------
__device__ __forceinline__ float wsum(float v) {
    #pragma unroll
    for (int o = 16; o; o >>= 1) v += __shfl_down_sync(0xffffffffu, v, o);
    return v;
}
__device__ __forceinline__ float wallsum(float v) {
    #pragma unroll
    for (int o = 16; o; o >>= 1) v += __shfl_xor_sync(0xffffffffu, v, o);
    return v;
}
__device__ __forceinline__ float wallmax(float v) {
    #pragma unroll
    for (int o = 16; o; o >>= 1) v = fmaxf(v, __shfl_xor_sync(0xffffffffu, v, o));
    return v;
}

// ---------------- K1: pearson sums + parity fold, inline hann ----------------
__global__ void __launch_bounds__(256) k_fold(const float* __restrict__ x,
                                              const float* __restrict__ y) {
    __shared__ float red[8][5];
    int b = blockIdx.x;
    int tid = threadIdx.x;
    int lane = tid & 31, warp = tid >> 5;

    const float* xr = x + (size_t)b * NN;
    const float* yr = y + (size_t)b * NN;
    const float W = 3.8349520e-4f;          // pi/8191

    float sx = 0.f, sy = 0.f, sxy = 0.f, sxx = 0.f, syy = 0.f;

    #pragma unroll 1
    for (int m = tid; m < MM2; m += 256) {
        float ge = 0.f, go = 0.f;
        #pragma unroll
        for (int j = 0; j < 10; j++) {
            int n = m + 900 * j;
            if (j < 9 || n < NN) {
                float xv = xr[n], yv = yr[n];
                sx  += xv;       sy  += yv;
                sxy += xv * yv;  sxx += xv * xv;  syy += yv * yv;
                float s = __sinf((float)n * W);
                float hx = xv * s * s;
                ge += hx;
                go += (j & 1) ? -hx : hx;
            }
        }
        d_fold[(size_t)b * MM2 + m] = make_float2(ge, go);
    }

    sx = wsum(sx); sy = wsum(sy); sxy = wsum(sxy); sxx = wsum(sxx); syy = wsum(syy);
    if (lane == 0) { red[warp][0]=sx; red[warp][1]=sy; red[warp][2]=sxy; red[warp][3]=sxx; red[warp][4]=syy; }
    __syncthreads();
    if (tid == 0) {
        double SX=0, SY=0, SXY=0, SXX=0, SYY=0;
        #pragma unroll
        for (int w = 0; w < 8; w++) {
            SX += red[w][0]; SY += red[w][1]; SXY += red[w][2];
            SXX += red[w][3]; SYY += red[w][4];
        }
        double num = (double)NN * SXY - SX * SY;
        double den = sqrt(((double)NN * SXX - SX * SX) * ((double)NN * SYY - SY * SY));
        d_tl[b] = (float)(1.0 - num / den);
    }
}

// ---------------- K2: 900-point parity NUDFT (R4 geometry, verbatim) --------
// grid (32 tiles, 9 chunks), block 288 = 36 tx * 8 ty; tile 4 rows x 4 bins
__global__ void __launch_bounds__(288, 2) k_dft() {
    __shared__ float sTab[SLAB * 2 * NBP];    // 10 m x 144 bins x (s,c)
    __shared__ float sGe[SLAB][32];
    __shared__ float sGo[SLAB][32];

    int tile  = blockIdx.x;
    int chunk = blockIdx.y;
    int tid = threadIdx.x;
    int tx = tid % 36;
    int ty = tid / 36;

    int rowBase = tile * 32;
    int mBase = chunk * CHM;

    int bk  = tid % NBP;
    int grp = tid / NBP;
    int freq = 40 + bk;

    ull acc[4][4] = {};
    const float* gp = (tx & 1) ? &sGo[0][0] : &sGe[0][0];
    const float ASCALE = 3.4906585e-3f;   // 2*pi/1800

    for (int step = 0; step < CHM / SLAB; step++) {
        int m0 = mBase + step * SLAB;
        __syncthreads();
        #pragma unroll
        for (int i = 0; i < 5; i++) {
            int mi = grp * 5 + i;
            float s = 0.f, c = 0.f;
            if (bk < NB) {
                int r = (freq * (m0 + mi)) % 1800;
                if (r >= 900) r -= 1800;
                __sincosf((float)r * ASCALE, &s, &c);
            }
            sTab[mi * (2 * NBP) + 2 * bk]     = s;
            sTab[mi * (2 * NBP) + 2 * bk + 1] = c;
        }
        if (tid < 160) {
            int r = tid & 31, q = tid >> 5;
            float4 v = *(const float4*)(d_fold + (size_t)(rowBase + r) * MM2 + m0 + 2 * q);
            sGe[2 * q][r]     = v.x;  sGo[2 * q][r]     = v.y;
            sGe[2 * q + 1][r] = v.z;  sGo[2 * q + 1][r] = v.w;
        }
        __syncthreads();

        #pragma unroll
        for (int mi = 0; mi < SLAB; mi++) {
            float4 g = *(const float4*)&gp[mi * 32 + 4 * ty];
            const ull* trow = (const ull*)&sTab[mi * (2 * NBP)];
            ull p0 = trow[tx];
            ull p1 = trow[tx + 36];
            ull p2 = trow[tx + 72];
            ull p3 = trow[tx + 108];
            float gr[4] = {g.x, g.y, g.z, g.w};
            #pragma unroll
            for (int r = 0; r < 4; r++) {
                ull g2 = pk2(gr[r], gr[r]);
                fma2(acc[r][0], g2, p0);
                fma2(acc[r][1], g2, p1);
                fma2(acc[r][2], g2, p2);
                fma2(acc[r][3], g2, p3);
            }
        }
    }

    #pragma unroll
    for (int r = 0; r < 4; r++) {
        int row = rowBase + 4 * ty + r;
        ull* dst = (ull*)(d_part + ((size_t)row * NCH + chunk) * NBP);
        dst[tx]       = acc[r][0];
        dst[tx + 36]  = acc[r][1];
        dst[tx + 72]  = acc[r][2];
        dst[tx + 108] = acc[r][3];
    }
}

// ---------------- K3: one block per row; thread = bin; NO fences/tickets -----
#define LT 160   // threads (5 warps); bins 0..143 active
__global__ void __launch_bounds__(LT) k_loss(const int* __restrict__ hr) {
    __shared__ float sh[8];
    __shared__ float shH;
    int tid = threadIdx.x;
    int lane = tid & 31, warp = tid >> 5;
    int row = blockIdx.x;
    bool valid = tid < NB;

    // sum chunk partials for this bin (coalesced, MLP=9, L2-hot in timed run)
    float s = 0.f, c = 0.f;
    if (valid) {
        const float2* pr = d_part + (size_t)row * NCH * NBP + tid;
        #pragma unroll
        for (int ch = 0; ch < NCH; ch++) {
            float2 v = pr[ch * NBP];
            s += v.x; c += v.y;
        }
    }
    float ca = valid ? (s * s + c * c) : 0.f;

    // tot
    float v = wallsum(ca);
    if (lane == 0) sh[warp] = v;
    __syncthreads();
    float tot = sh[0] + sh[1] + sh[2] + sh[3] + sh[4];
    __syncthreads();

    float logit = ca / tot;

    // max
    v = wallmax(valid ? logit : -1e30f);
    if (lane == 0) sh[warp] = v;
    __syncthreads();
    float mx = fmaxf(fmaxf(fmaxf(sh[0], sh[1]), fmaxf(sh[2], sh[3])), sh[4]);
    __syncthreads();

    // logsumexp
    v = wallsum(valid ? expf(logit - mx) : 0.f);
    if (lane == 0) sh[warp] = v;
    __syncthreads();
    float lse = mx + logf(sh[0] + sh[1] + sh[2] + sh[3] + sh[4]);

    int h = hr[row];
    if (tid == h) shH = logit;
    __syncthreads();
    float ce = lse - shH;
    __syncthreads();

    // kl
    float klc = 0.f;
    if (valid) {
        float dd = (float)tid - (float)h;
        float t = expf(-0.5f * dd * dd) * 0.3989422804014327f;
        t = fmaxf(t, 1e-15f);
        klc = expf(t) * (t - (logit - lse));
    }
    v = wallsum(klc);
    if (lane == 0) sh[warp] = v;
    __syncthreads();
    if (tid == 0) d_fl[row] = ce + (sh[0] + sh[1] + sh[2] + sh[3] + sh[4]) / (float)NB;
}

// ---------------- K4: final scalar ----------------
__global__ void __launch_bounds__(1024) k_final(const int* __restrict__ epoch_p,
                                                float* __restrict__ out) {
    __shared__ float r1[32], r2[32];
    int tid = threadIdx.x, lane = tid & 31, warp = tid >> 5;
    float a = d_tl[tid], c = d_fl[tid];
    a = wsum(a); c = wsum(c);
    if (lane == 0) { r1[warp] = a; r2[warp] = c; }
    __syncthreads();
    if (warp == 0) {
        a = wsum(r1[lane]);
        c = wsum(r2[lane]);
        if (lane == 0) {
            double tl = (double)a / (double)BB;
            double fl = (double)c / (double)BB;
            int epoch = epoch_p[0];
            double alpha, beta;
            if (epoch > 25) { alpha = 0.05; beta = 2.0; }
            else {
                alpha = 0.1 * pow(0.5, (double)epoch / 25.0);
                beta  = pow(2.0, (double)epoch / 25.0);
            }
            out[0] = (float)(alpha * tl + beta * fl);
        }
    }
}

// ---------------- launch ----------------
extern "C" void kernel_launch(void* const* d_in, const int* in_sizes, int n_in,
                              void* d_out, int out_size) {
    const int*   epoch_p = nullptr;
    const float* xp = nullptr;
    const float* yp = nullptr;
    const int*   hrp = nullptr;
    for (int i = 0; i < n_in; i++) {
        if (in_sizes[i] == 1 && !epoch_p) epoch_p = (const int*)d_in[i];
        else if (in_sizes[i] == BB * NN) { if (!xp) xp = (const float*)d_in[i]; else yp = (const float*)d_in[i]; }
        else if (in_sizes[i] == BB) hrp = (const int*)d_in[i];
    }
    float* out = (float*)d_out;

    k_fold<<<BB, 256>>>(xp, yp);
    k_dft<<<dim3(32, NCH), 288>>>();
    k_loss<<<BB, LT>>>(hrp);
    k_final<<<1, 1024>>>(epoch_p, out);
    (void)out_size;
}

// round 9
// speedup vs baseline: 2.0729x; 1.0825x over previous
#include <cuda_runtime.h>
#include <math.h>
#include <stdint.h>

#define BB    1024     // batch rows
#define NN    8192     // samples per row
#define MM2   900      // half fold period (parity decimation)
#define NB    140      // bpm bins
#define NBP   144      // padded bins
#define NCH   9        // m-chunks
#define CHM   100      // m per chunk (9*100 = 900)
#define SLAB  10       // m per smem slab

// ---------------- device scratch ----------------
__device__ float2 d_fold[(size_t)BB * MM2];             // (ge, go)
__device__ float2 d_part[(size_t)BB * NCH * NBP];       // [row][chunk][bin] (s,c)
__device__ float  d_tl[BB];
__device__ float  d_fl[BB];

typedef unsigned long long ull;

// ---------------- f32x2 helpers ----------------
__device__ __forceinline__ ull pk2(float lo, float hi) {
    ull r;
    asm("mov.b64 %0, {%1, %2};" : "=l"(r) : "f"(lo), "f"(hi));
    return r;
}
__device__ __forceinline__ void fma2(ull& d, ull a, ull b) {
    asm("fma.rn.f32x2 %0, %1, %2, %0;" : "+l"(d) : "l"(a), "l"(b));
}

// ---------------- warp helpers ----------------
__device__ __forceinline__ float wsum(float v) {
    #pragma unroll
    for (int o = 16; o; o >>= 1) v += __shfl_down_sync(0xffffffffu, v, o);
    return v;
}
__device__ __forceinline__ float wallsum(float v) {
    #pragma unroll
    for (int o = 16; o; o >>= 1) v += __shfl_xor_sync(0xffffffffu, v, o);
    return v;
}
__device__ __forceinline__ float wallmax(float v) {
    #pragma unroll
    for (int o = 16; o; o >>= 1) v = fmaxf(v, __shfl_xor_sync(0xffffffffu, v, o));
    return v;
}

// ---------------- K1: pearson + parity fold, float4 (MLP ~20), inline hann ---
// thread t<225 owns m in {4t..4t+3}; float4 index q = t + 225*j is 16B-aligned
__global__ void __launch_bounds__(256) k_fold(const float* __restrict__ x,
                                              const float* __restrict__ y) {
    __shared__ float red[8][5];
    int b = blockIdx.x;
    int tid = threadIdx.x;
    int lane = tid & 31, warp = tid >> 5;

    const float4* xr = (const float4*)(x + (size_t)b * NN);
    const float4* yr = (const float4*)(y + (size_t)b * NN);
    const float W = 3.8349520e-4f;          // pi/8191

    float sx = 0.f, sy = 0.f, sxy = 0.f, sxx = 0.f, syy = 0.f;
    float ge[4] = {}, go[4] = {};

    if (tid < 225) {
        #pragma unroll
        for (int j = 0; j < 10; j++) {
            int q = tid + 225 * j;                   // float4 index
            if (j < 9 || q < 2048) {
                float4 xv = xr[q];
                float4 yv = yr[q];
                sx += xv.x + xv.y + xv.z + xv.w;
                sy += yv.x + yv.y + yv.z + yv.w;
                sxy += xv.x*yv.x + xv.y*yv.y + xv.z*yv.z + xv.w*yv.w;
                sxx += xv.x*xv.x + xv.y*xv.y + xv.z*xv.z + xv.w*xv.w;
                syy += yv.x*yv.x + yv.y*yv.y + yv.z*yv.z + yv.w*yv.w;
                int n = 4 * q;
                float s0 = __sinf((float)(n)     * W);
                float s1 = __sinf((float)(n + 1) * W);
                float s2 = __sinf((float)(n + 2) * W);
                float s3 = __sinf((float)(n + 3) * W);
                float h0 = xv.x * s0 * s0, h1 = xv.y * s1 * s1;
                float h2 = xv.z * s2 * s2, h3 = xv.w * s3 * s3;
                ge[0] += h0; ge[1] += h1; ge[2] += h2; ge[3] += h3;
                if (j & 1) { go[0] -= h0; go[1] -= h1; go[2] -= h2; go[3] -= h3; }
                else       { go[0] += h0; go[1] += h1; go[2] += h2; go[3] += h3; }
            }
        }
        float4* dst = (float4*)(d_fold + (size_t)b * MM2 + 4 * tid);
        dst[0] = make_float4(ge[0], go[0], ge[1], go[1]);
        dst[1] = make_float4(ge[2], go[2], ge[3], go[3]);
    }

    sx = wsum(sx); sy = wsum(sy); sxy = wsum(sxy); sxx = wsum(sxx); syy = wsum(syy);
    if (lane == 0) { red[warp][0]=sx; red[warp][1]=sy; red[warp][2]=sxy; red[warp][3]=sxx; red[warp][4]=syy; }
    __syncthreads();
    if (tid == 0) {
        double SX=0, SY=0, SXY=0, SXX=0, SYY=0;
        #pragma unroll
        for (int w = 0; w < 8; w++) {
            SX += red[w][0]; SY += red[w][1]; SXY += red[w][2];
            SXX += red[w][3]; SYY += red[w][4];
        }
        double num = (double)NN * SXY - SX * SY;
        double den = sqrt(((double)NN * SXX - SX * SX) * ((double)NN * SYY - SY * SY));
        d_tl[b] = (float)(1.0 - num / den);
    }
}

// ---------------- K2: 900-point parity NUDFT (R4 geometry, verbatim) --------
// grid (32 tiles, 9 chunks), block 288 = 36 tx * 8 ty; tile 4 rows x 4 bins
__global__ void __launch_bounds__(288, 2) k_dft() {
    __shared__ float sTab[SLAB * 2 * NBP];    // 10 m x 144 bins x (s,c)
    __shared__ float sGe[SLAB][32];
    __shared__ float sGo[SLAB][32];

    int tile  = blockIdx.x;
    int chunk = blockIdx.y;
    int tid = threadIdx.x;
    int tx = tid % 36;
    int ty = tid / 36;

    int rowBase = tile * 32;
    int mBase = chunk * CHM;

    int bk  = tid % NBP;
    int grp = tid / NBP;
    int freq = 40 + bk;

    ull acc[4][4] = {};
    const float* gp = (tx & 1) ? &sGo[0][0] : &sGe[0][0];
    const float ASCALE = 3.4906585e-3f;   // 2*pi/1800

    for (int step = 0; step < CHM / SLAB; step++) {
        int m0 = mBase + step * SLAB;
        __syncthreads();
        #pragma unroll
        for (int i = 0; i < 5; i++) {
            int mi = grp * 5 + i;
            float s = 0.f, c = 0.f;
            if (bk < NB) {
                int r = (freq * (m0 + mi)) % 1800;
                if (r >= 900) r -= 1800;
                __sincosf((float)r * ASCALE, &s, &c);
            }
            sTab[mi * (2 * NBP) + 2 * bk]     = s;
            sTab[mi * (2 * NBP) + 2 * bk + 1] = c;
        }
        if (tid < 160) {
            int r = tid & 31, q = tid >> 5;
            float4 v = *(const float4*)(d_fold + (size_t)(rowBase + r) * MM2 + m0 + 2 * q);
            sGe[2 * q][r]     = v.x;  sGo[2 * q][r]     = v.y;
            sGe[2 * q + 1][r] = v.z;  sGo[2 * q + 1][r] = v.w;
        }
        __syncthreads();

        #pragma unroll
        for (int mi = 0; mi < SLAB; mi++) {
            float4 g = *(const float4*)&gp[mi * 32 + 4 * ty];
            const ull* trow = (const ull*)&sTab[mi * (2 * NBP)];
            ull p0 = trow[tx];
            ull p1 = trow[tx + 36];
            ull p2 = trow[tx + 72];
            ull p3 = trow[tx + 108];
            float gr[4] = {g.x, g.y, g.z, g.w};
            #pragma unroll
            for (int r = 0; r < 4; r++) {
                ull g2 = pk2(gr[r], gr[r]);
                fma2(acc[r][0], g2, p0);
                fma2(acc[r][1], g2, p1);
                fma2(acc[r][2], g2, p2);
                fma2(acc[r][3], g2, p3);
            }
        }
    }

    #pragma unroll
    for (int r = 0; r < 4; r++) {
        int row = rowBase + 4 * ty + r;
        ull* dst = (ull*)(d_part + ((size_t)row * NCH + chunk) * NBP);
        dst[tx]       = acc[r][0];
        dst[tx + 36]  = acc[r][1];
        dst[tx + 72]  = acc[r][2];
        dst[tx + 108] = acc[r][3];
    }
}

// ---------------- K3: one block per row; thread = bin; no fences -------------
#define LT 160   // threads (5 warps); bins 0..143 active
__global__ void __launch_bounds__(LT) k_loss(const int* __restrict__ hr) {
    __shared__ float sh[8];
    __shared__ float shH;
    int tid = threadIdx.x;
    int lane = tid & 31, warp = tid >> 5;
    int row = blockIdx.x;
    bool valid = tid < NB;

    float s = 0.f, c = 0.f;
    if (valid) {
        const float2* pr = d_part + (size_t)row * NCH * NBP + tid;
        #pragma unroll
        for (int ch = 0; ch < NCH; ch++) {
            float2 v = pr[ch * NBP];
            s += v.x; c += v.y;
        }
    }
    float ca = valid ? (s * s + c * c) : 0.f;

    float v = wallsum(ca);
    if (lane == 0) sh[warp] = v;
    __syncthreads();
    float tot = sh[0] + sh[1] + sh[2] + sh[3] + sh[4];
    __syncthreads();

    float logit = ca / tot;

    v = wallmax(valid ? logit : -1e30f);
    if (lane == 0) sh[warp] = v;
    __syncthreads();
    float mx = fmaxf(fmaxf(fmaxf(sh[0], sh[1]), fmaxf(sh[2], sh[3])), sh[4]);
    __syncthreads();

    v = wallsum(valid ? expf(logit - mx) : 0.f);
    if (lane == 0) sh[warp] = v;
    __syncthreads();
    float lse = mx + logf(sh[0] + sh[1] + sh[2] + sh[3] + sh[4]);

    int h = hr[row];
    if (tid == h) shH = logit;
    __syncthreads();
    float ce = lse - shH;
    __syncthreads();

    float klc = 0.f;
    if (valid) {
        float dd = (float)tid - (float)h;
        float t = expf(-0.5f * dd * dd) * 0.3989422804014327f;
        t = fmaxf(t, 1e-15f);
        klc = expf(t) * (t - (logit - lse));
    }
    v = wallsum(klc);
    if (lane == 0) sh[warp] = v;
    __syncthreads();
    if (tid == 0) d_fl[row] = ce + (sh[0] + sh[1] + sh[2] + sh[3] + sh[4]) / (float)NB;
}

// ---------------- K4: final scalar (no FP64 pow) ----------------
__global__ void __launch_bounds__(1024) k_final(const int* __restrict__ epoch_p,
                                                float* __restrict__ out) {
    __shared__ float r1[32], r2[32];
    int tid = threadIdx.x, lane = tid & 31, warp = tid >> 5;
    float a = d_tl[tid], c = d_fl[tid];
    a = wsum(a); c = wsum(c);
    if (lane == 0) { r1[warp] = a; r2[warp] = c; }
    __syncthreads();
    if (warp == 0) {
        a = wsum(r1[lane]);
        c = wsum(r2[lane]);
        if (lane == 0) {
            float tl = a / (float)BB;
            float fl = c / (float)BB;
            int epoch = epoch_p[0];
            float alpha, beta;
            if (epoch > 25) { alpha = 0.05f; beta = 2.0f; }
            else {
                float e = (float)epoch * 0.04f;       // epoch/25
                alpha = 0.1f * exp2f(-e);
                beta  = exp2f(e);
            }
            out[0] = alpha * tl + beta * fl;
        }
    }
}

// ---------------- launch ----------------
extern "C" void kernel_launch(void* const* d_in, const int* in_sizes, int n_in,
                              void* d_out, int out_size) {
    const int*   epoch_p = nullptr;
    const float* xp = nullptr;
    const float* yp = nullptr;
    const int*   hrp = nullptr;
    for (int i = 0; i < n_in; i++) {
        if (in_sizes[i] == 1 && !epoch_p) epoch_p = (const int*)d_in[i];
        else if (in_sizes[i] == BB * NN) { if (!xp) xp = (const float*)d_in[i]; else yp = (const float*)d_in[i]; }
        else if (in_sizes[i] == BB) hrp = (const int*)d_in[i];
    }
    float* out = (float*)d_out;

    k_fold<<<BB, 256>>>(xp, yp);
    k_dft<<<dim3(32, NCH), 288>>>();
    k_loss<<<BB, LT>>>(hrp);
    k_final<<<1, 1024>>>(epoch_p, out);
    (void)out_size;
}